// round 15
// baseline (speedup 1.0000x reference)
#include <cuda_runtime.h>
#include <cuda_fp16.h>
#include <math.h>
#include <stdint.h>

#define NN 100000
#define NE 3200000
#define MAXD 256

typedef unsigned long long ull;

// ---------------- static device scratch (allocation-free contract) ----------------
__device__ float  g_bufA[(size_t)NN * MAXD];
__device__ float  g_bufB[(size_t)NN * MAXD];
__device__ float  g_bufC[(size_t)NN * MAXD];
__device__ int    g_src[NE];
__device__ int    g_dst[NE];
__device__ int    g_cnt[NN];       // invariant: zero at entry
__device__ int    g_rowptr[NN + 1];
__device__ int    g_woff[NN];
__device__ int2   g_csre[NE];      // packed {src, weight-bits}
__device__ float  g_di[NN];
__device__ float  g_dis[NN];
__device__ float  g_bn[512];       // invariant: zero at entry (finalize re-zeroes)
__device__ float  g_scale[256];
__device__ float  g_shift[256];

__device__ __forceinline__ unsigned pack_h2(float a, float b) {
    __half2 h = __floats2half2_rn(a, b);
    return *reinterpret_cast<unsigned*>(&h);
}
__device__ __forceinline__ float2 unpack_h2(unsigned u) {
    __half2 h = *reinterpret_cast<__half2*>(&u);
    return __half22float2(h);
}

#define MMA_F16(c, a, b)                                                               \
    asm volatile(                                                                      \
        "mma.sync.aligned.m16n8k16.row.col.f32.f16.f16.f32 "                           \
        "{%0,%1,%2,%3},{%4,%5,%6,%7},{%8,%9},{%0,%1,%2,%3};"                           \
        : "+f"((c)[0]), "+f"((c)[1]), "+f"((c)[2]), "+f"((c)[3])                       \
        : "r"((a)[0]), "r"((a)[1]), "r"((a)[2]), "r"((a)[3]), "r"((b)[0]), "r"((b)[1]))

#define LDSM_X4(r0, r1, r2, r3, addr)                                                  \
    asm volatile("ldmatrix.sync.aligned.m8n8.x4.shared.b16 {%0,%1,%2,%3}, [%4];"       \
                 : "=r"(r0), "=r"(r1), "=r"(r2), "=r"(r3) : "r"(addr))

// ---------------- prep: detect dtype inline, convert, count in-degree ----------------
__global__ void k_prep_edges(const void* __restrict__ ei_raw,
                             int* __restrict__ src, int* __restrict__ dst,
                             int* __restrict__ cnt, int E, int n) {
    const unsigned int* w = (const unsigned int*)ei_raw;
    unsigned int probe = w[2 * (threadIdx.x & 255) + 1];
    int any = __syncthreads_or(probe != 0u);
    const int is64 = (any == 0);
    const long long* ei64 = (const long long*)ei_raw;
    const int* ei32 = (const int*)ei_raw;
    for (int e = blockIdx.x * blockDim.x + threadIdx.x; e < E; e += gridDim.x * blockDim.x) {
        int s, d;
        if (is64) { s = (int)ei64[e]; d = (int)ei64[(size_t)E + e]; }
        else      { s = ei32[e];      d = ei32[(size_t)E + e]; }
        if ((unsigned)s >= (unsigned)n) s = 0;
        if ((unsigned)d >= (unsigned)n) d = 0;
        src[e] = s;
        dst[e] = d;
        atomicAdd(&cnt[d], 1);
    }
}

// ---------------- single-block tiled coalesced scan + deg + cnt re-zero ----------------
__global__ void k_scan_deg(int* __restrict__ cnt, int* __restrict__ rowptr,
                           int* __restrict__ woff, float* __restrict__ di,
                           float* __restrict__ dis, int n) {
    __shared__ int wsum[32];
    __shared__ int s_off;
    int t = threadIdx.x, lane = t & 31, wid = t >> 5;
    if (t == 0) s_off = 0;
    __syncthreads();
    for (int base = 0; base < n; base += 1024) {
        int i = base + t;
        int c = (i < n) ? cnt[i] : 0;
        if (i < n) cnt[i] = 0;
        int x = c;
#pragma unroll
        for (int o = 1; o < 32; o <<= 1) {
            int v = __shfl_up_sync(0xffffffffu, x, o);
            if (lane >= o) x += v;
        }
        if (lane == 31) wsum[wid] = x;
        __syncthreads();
        if (wid == 0) {
            int y = wsum[lane];
#pragma unroll
            for (int o = 1; o < 32; o <<= 1) {
                int v = __shfl_up_sync(0xffffffffu, y, o);
                if (lane >= o) y += v;
            }
            wsum[lane] = y;
        }
        __syncthreads();
        int wbase = (wid == 0) ? 0 : wsum[wid - 1];
        int excl = x + wbase - c;
        int off0 = s_off;
        if (i < n) {
            int r = off0 + excl;
            rowptr[i] = r;
            woff[i]   = r;
            float dg = (float)c + 1.0f;
            di[i]  = 1.0f / dg;
            dis[i] = rsqrtf(dg);
        }
        __syncthreads();
        if (t == 1023) s_off = off0 + wsum[31];
        __syncthreads();
    }
    if (t == 0) rowptr[n] = s_off;
}

// ---------------- CSR scatter with packed (src, weight) ----------------
__global__ void k_csr(const int* __restrict__ src, const int* __restrict__ dst,
                      const float* __restrict__ dis, int* __restrict__ woff,
                      int2* __restrict__ csre, int E) {
    for (int e = blockIdx.x * blockDim.x + threadIdx.x; e < E; e += gridDim.x * blockDim.x) {
        int d = dst[e];
        int pos = atomicAdd(&woff[d], 1);
        int s = src[e];
        if (pos < E) {
            float w = dis[s] * dis[d];
            csre[pos] = make_int2(s, __float_as_int(w));
        }
    }
}

// ---------------- half aggregation: warp-per-node, half2 lanes, 2-edge unroll ----------------
template <int D, bool EPI, bool AFF>
__global__ __launch_bounds__(256) void k_aggh(
    const __half* __restrict__ xin, __half* __restrict__ xout,
    const int* __restrict__ rowptr, const int2* __restrict__ csre,
    const float* __restrict__ di, int n,
    const float* __restrict__ scale, const float* __restrict__ shift,
    const float* __restrict__ bias, float* __restrict__ bnsum, float* __restrict__ bnsq)
{
    constexpr int CPL2 = D / 64;
    int lane = threadIdx.x & 31;
    int node = blockIdx.x * 8 + (threadIdx.x >> 5);
    float2 acc[CPL2];
    float2 sc[CPL2], sh[CPL2];
#pragma unroll
    for (int j = 0; j < CPL2; j++) {
        acc[j] = make_float2(0.f, 0.f);
        if (AFF) {
            int f = 2 * lane + 64 * j;
            sc[j] = make_float2(scale[f], scale[f + 1]);
            sh[j] = make_float2(shift[f], shift[f + 1]);
        }
    }

    if (node < n) {
        int beg = rowptr[node], end = rowptr[node + 1];
        int e = beg;
        for (; e + 2 <= end; e += 2) {
            int2 p0 = __ldg(&csre[e]);
            int2 p1 = __ldg(&csre[e + 1]);
            float w0 = __int_as_float(p0.y);
            float w1 = __int_as_float(p1.y);
            const __half2* r0 = (const __half2*)(xin + (size_t)p0.x * D) + lane;
            const __half2* r1 = (const __half2*)(xin + (size_t)p1.x * D) + lane;
            __half2 h0[CPL2], h1[CPL2];
#pragma unroll
            for (int j = 0; j < CPL2; j++) h0[j] = __ldg(r0 + 32 * j);
#pragma unroll
            for (int j = 0; j < CPL2; j++) h1[j] = __ldg(r1 + 32 * j);
#pragma unroll
            for (int j = 0; j < CPL2; j++) {
                float2 v0 = __half22float2(h0[j]);
                float2 v1 = __half22float2(h1[j]);
                if (AFF) {
                    v0.x = fmaxf(v0.x * sc[j].x + sh[j].x, 0.f);
                    v0.y = fmaxf(v0.y * sc[j].y + sh[j].y, 0.f);
                    v1.x = fmaxf(v1.x * sc[j].x + sh[j].x, 0.f);
                    v1.y = fmaxf(v1.y * sc[j].y + sh[j].y, 0.f);
                }
                acc[j].x += w0 * v0.x + w1 * v1.x;
                acc[j].y += w0 * v0.y + w1 * v1.y;
            }
        }
        if (e < end) {
            int2 p0 = __ldg(&csre[e]);
            float w0 = __int_as_float(p0.y);
            const __half2* r0 = (const __half2*)(xin + (size_t)p0.x * D) + lane;
#pragma unroll
            for (int j = 0; j < CPL2; j++) {
                float2 v = __half22float2(__ldg(r0 + 32 * j));
                if (AFF) {
                    v.x = fmaxf(v.x * sc[j].x + sh[j].x, 0.f);
                    v.y = fmaxf(v.y * sc[j].y + sh[j].y, 0.f);
                }
                acc[j].x += w0 * v.x;
                acc[j].y += w0 * v.y;
            }
        }
        float dii = di[node];
        const __half2* r = (const __half2*)(xin + (size_t)node * D) + lane;
        __half2* orow = (__half2*)(xout + (size_t)node * D);
#pragma unroll
        for (int j = 0; j < CPL2; j++) {
            float2 v = __half22float2(__ldg(r + 32 * j));
            if (AFF) {
                v.x = fmaxf(v.x * sc[j].x + sh[j].x, 0.f);
                v.y = fmaxf(v.y * sc[j].y + sh[j].y, 0.f);
            }
            acc[j].x += dii * v.x;
            acc[j].y += dii * v.y;
            if (EPI) {
                int f = 2 * lane + 64 * j;
                acc[j].x += bias[f];
                acc[j].y += bias[f + 1];
            }
            orow[lane + 32 * j] = __floats2half2_rn(acc[j].x, acc[j].y);
        }
    }
    if constexpr (EPI) {
        __shared__ float csum[D];
        __shared__ float csq[D];
        for (int t = threadIdx.x; t < D; t += blockDim.x) { csum[t] = 0.f; csq[t] = 0.f; }
        __syncthreads();
        if (node < n) {
#pragma unroll
            for (int j = 0; j < CPL2; j++) {
                int f = 2 * lane + 64 * j;
                atomicAdd(&csum[f], acc[j].x);
                atomicAdd(&csum[f + 1], acc[j].y);
                atomicAdd(&csq[f], acc[j].x * acc[j].x);
                atomicAdd(&csq[f + 1], acc[j].y * acc[j].y);
            }
        }
        __syncthreads();
        for (int t = threadIdx.x; t < D; t += blockDim.x) {
            atomicAdd(&bnsum[t], csum[t]);
            atomicAdd(&bnsq[t], csq[t]);
        }
    }
}

// ---------------- fp32-input aggregation (L4, D=32) -> half out + stats ----------------
__global__ __launch_bounds__(256) void k_agg32(
    const float* __restrict__ xin, __half* __restrict__ xout,
    const int* __restrict__ rowptr, const int2* __restrict__ csre,
    const float* __restrict__ di, int n,
    const float* __restrict__ bias, float* __restrict__ bnsum, float* __restrict__ bnsq)
{
    int lane = threadIdx.x & 31;
    int node = blockIdx.x * 8 + (threadIdx.x >> 5);
    float acc = 0.f;

    if (node < n) {
        int beg = rowptr[node], end = rowptr[node + 1];
        int e = beg;
        for (; e + 2 <= end; e += 2) {
            int2 p0 = __ldg(&csre[e]);
            int2 p1 = __ldg(&csre[e + 1]);
            float v0 = __ldg(xin + (size_t)p0.x * 32 + lane);
            float v1 = __ldg(xin + (size_t)p1.x * 32 + lane);
            acc += __int_as_float(p0.y) * v0;
            acc += __int_as_float(p1.y) * v1;
        }
        if (e < end) {
            int2 p0 = __ldg(&csre[e]);
            acc += __int_as_float(p0.y) * __ldg(xin + (size_t)p0.x * 32 + lane);
        }
        acc += di[node] * __ldg(xin + (size_t)node * 32 + lane);
        acc += bias[lane];
        xout[(size_t)node * 32 + lane] = __float2half_rn(acc);
    }
    __shared__ float csum[32];
    __shared__ float csq[32];
    if (threadIdx.x < 32) { csum[threadIdx.x] = 0.f; csq[threadIdx.x] = 0.f; }
    __syncthreads();
    if (node < n) {
        atomicAdd(&csum[lane], acc);
        atomicAdd(&csq[lane], acc * acc);
    }
    __syncthreads();
    if (threadIdx.x < 32) {
        atomicAdd(&bnsum[threadIdx.x], csum[threadIdx.x]);
        atomicAdd(&bnsq[threadIdx.x], csq[threadIdx.x]);
    }
}

// ---------------- fp16 tensor-core GEMM: double-buffered smem + ldmatrix ----------------
template <bool EPI, bool AFF, bool OUTH, bool A16>
__global__ __launch_bounds__(256, 3) void k_gemm16(
    const void* __restrict__ Ain, const float* __restrict__ W, void* __restrict__ Cout,
    int M, int K, int Nc,
    const float* __restrict__ scale, const float* __restrict__ shift,
    const float* __restrict__ bias, float* __restrict__ bnsum, float* __restrict__ bnsq)
{
    __shared__ unsigned As[2][128][20];
    __shared__ unsigned Bs[2][64][20];
    constexpr uint32_t A_BUF_BYTES = 128 * 20 * 4;
    constexpr uint32_t B_BUF_BYTES = 64 * 20 * 4;
    int tid = threadIdx.x;
    int row0 = blockIdx.y * 128, col0 = blockIdx.x * 64;
    int w = tid >> 5, lane = tid & 31;
    int wm = w & 3, wn = w >> 2;
    int g = lane >> 2, t = lane & 3;

    float acc[2][4][4];
#pragma unroll
    for (int mi = 0; mi < 2; mi++)
#pragma unroll
        for (int ni = 0; ni < 4; ni++)
#pragma unroll
            for (int q = 0; q < 4; q++) acc[mi][ni][q] = 0.f;

    uint32_t asb = (uint32_t)__cvta_generic_to_shared(&As[0][0][0]);
    uint32_t bsb = (uint32_t)__cvta_generic_to_shared(&Bs[0][0][0]);
    int l16 = lane & 15, kh = lane >> 4;
    int l8 = lane & 7, quad = lane >> 3;
    uint32_t aA = asb + (((wm * 32 + l16) * 20 + 4 * kh) << 2);
    uint32_t aB = bsb + (((wn * 32 + (quad >> 1) * 8 + l8) * 20 + 4 * (quad & 1)) << 2);

    uint4  pa16[2];
    float4 pa32[4];
    float  pb[4][2];

    int a16_m = tid >> 2, a16_seg = tid & 3;
    int a32_m = tid >> 3, a32_seg = tid & 7;
    int b_nn = tid & 63, b_kp0 = tid >> 6;

    const __half* A16p = (const __half*)Ain;
    const float*  A32p = (const float*)Ain;

    auto loadA = [&](int k0) {
        if (A16) {
#pragma unroll
            for (int it = 0; it < 2; it++) {
                int m = a16_m + 64 * it;
                int gm = row0 + m;
                uint4 v = make_uint4(0u, 0u, 0u, 0u);
                if (gm < M) v = *(const uint4*)(A16p + (size_t)gm * K + k0 + 8 * a16_seg);
                pa16[it] = v;
            }
        } else {
#pragma unroll
            for (int it = 0; it < 4; it++) {
                int m = a32_m + 32 * it;
                int gm = row0 + m;
                float4 v = make_float4(0.f, 0.f, 0.f, 0.f);
                if (gm < M) v = *(const float4*)(A32p + (size_t)gm * K + k0 + 4 * a32_seg);
                pa32[it] = v;
            }
        }
    };
    auto loadB = [&](int k0) {
        int gc = col0 + b_nn;
        bool ok = gc < Nc;
#pragma unroll
        for (int it = 0; it < 4; it++) {
            int kp = b_kp0 + 4 * it;
            pb[it][0] = ok ? W[(size_t)(k0 + 2 * kp) * Nc + gc] : 0.f;
            pb[it][1] = ok ? W[(size_t)(k0 + 2 * kp + 1) * Nc + gc] : 0.f;
        }
    };
    auto storeA = [&](int k0, int buf) {
        if (A16) {
#pragma unroll
            for (int it = 0; it < 2; it++) {
                int m = a16_m + 64 * it;
                uint4 v = pa16[it];
                if (AFF) {
                    unsigned* pv = &v.x;
#pragma unroll
                    for (int i = 0; i < 4; i++) {
                        float2 f = unpack_h2(pv[i]);
                        int c = k0 + 8 * a16_seg + 2 * i;
                        f.x = fmaxf(f.x * scale[c] + shift[c], 0.f);
                        f.y = fmaxf(f.y * scale[c + 1] + shift[c + 1], 0.f);
                        pv[i] = pack_h2(f.x, f.y);
                    }
                }
                *(uint4*)&As[buf][m][4 * a16_seg] = v;
            }
        } else {
#pragma unroll
            for (int it = 0; it < 4; it++) {
                int m = a32_m + 32 * it;
                float4 v = pa32[it];
                if (AFF) {
                    int c = k0 + 4 * a32_seg;
                    v.x = fmaxf(v.x * scale[c + 0] + shift[c + 0], 0.f);
                    v.y = fmaxf(v.y * scale[c + 1] + shift[c + 1], 0.f);
                    v.z = fmaxf(v.z * scale[c + 2] + shift[c + 2], 0.f);
                    v.w = fmaxf(v.w * scale[c + 3] + shift[c + 3], 0.f);
                }
                uint2 p = make_uint2(pack_h2(v.x, v.y), pack_h2(v.z, v.w));
                *(uint2*)&As[buf][m][2 * a32_seg] = p;
            }
        }
    };
    auto storeB = [&](int buf) {
#pragma unroll
        for (int it = 0; it < 4; it++) {
            int kp = b_kp0 + 4 * it;
            Bs[buf][b_nn][kp] = pack_h2(pb[it][0], pb[it][1]);
        }
    };

    loadA(0);
    loadB(0);
    storeA(0, 0);
    storeB(0);
    __syncthreads();

    const int nchunks = K >> 5;
    for (int c = 0; c < nchunks; c++) {
        int b = c & 1;
        bool more = (c + 1 < nchunks);
        if (more) {
            loadA(32 * (c + 1));
            loadB(32 * (c + 1));
        }
        uint32_t aOff = (uint32_t)b * A_BUF_BYTES;
        uint32_t bOff = (uint32_t)b * B_BUF_BYTES;
#pragma unroll
        for (int ks = 0; ks < 2; ks++) {
            uint32_t koff = (8 * ks) << 2;
            unsigned a0[4], a1[4];
            LDSM_X4(a0[0], a0[1], a0[2], a0[3], aA + aOff + koff);
            LDSM_X4(a1[0], a1[1], a1[2], a1[3], aA + aOff + koff + 16 * 20 * 4);
#pragma unroll
            for (int p = 0; p < 2; p++) {
                unsigned r0, r1, r2, r3;
                LDSM_X4(r0, r1, r2, r3, aB + bOff + koff + p * (16 * 20 * 4));
                unsigned bA[2] = {r0, r1};
                unsigned bB[2] = {r2, r3};
                MMA_F16(acc[0][2 * p + 0], a0, bA);
                MMA_F16(acc[1][2 * p + 0], a1, bA);
                MMA_F16(acc[0][2 * p + 1], a0, bB);
                MMA_F16(acc[1][2 * p + 1], a1, bB);
            }
        }
        if (more) {
            storeA(32 * (c + 1), 1 - b);
            storeB(1 - b);
            __syncthreads();
        }
    }

    if constexpr (!EPI) {
#pragma unroll
        for (int mi = 0; mi < 2; mi++) {
            int rt = row0 + wm * 32 + mi * 16 + g;
#pragma unroll
            for (int ni = 0; ni < 4; ni++) {
                int gc = col0 + wn * 32 + ni * 8 + 2 * t;
                if (gc < Nc) {
                    if (rt < M) {
                        if (OUTH)
                            *(unsigned*)((__half*)Cout + (size_t)rt * Nc + gc) =
                                pack_h2(acc[mi][ni][0], acc[mi][ni][1]);
                        else
                            *(float2*)((float*)Cout + (size_t)rt * Nc + gc) =
                                make_float2(acc[mi][ni][0], acc[mi][ni][1]);
                    }
                    if (rt + 8 < M) {
                        if (OUTH)
                            *(unsigned*)((__half*)Cout + (size_t)(rt + 8) * Nc + gc) =
                                pack_h2(acc[mi][ni][2], acc[mi][ni][3]);
                        else
                            *(float2*)((float*)Cout + (size_t)(rt + 8) * Nc + gc) =
                                make_float2(acc[mi][ni][2], acc[mi][ni][3]);
                    }
                }
            }
        }
    } else {
        __shared__ float csum[64];
        __shared__ float csq[64];
        __syncthreads();
        if (tid < 64) { csum[tid] = 0.f; csq[tid] = 0.f; }
        __syncthreads();
#pragma unroll
        for (int ni = 0; ni < 4; ni++) {
            int cl = wn * 32 + ni * 8 + 2 * t;
            int gc = col0 + cl;
            if (gc >= Nc) continue;
            float b0 = bias[gc], b1 = bias[gc + 1];
            float s0 = 0.f, s1 = 0.f, q0 = 0.f, q1 = 0.f;
#pragma unroll
            for (int mi = 0; mi < 2; mi++) {
                int rt = row0 + wm * 32 + mi * 16 + g;
                if (rt < M) {
                    float v0 = acc[mi][ni][0] + b0;
                    float v1 = acc[mi][ni][1] + b1;
                    if (OUTH)
                        *(unsigned*)((__half*)Cout + (size_t)rt * Nc + gc) = pack_h2(v0, v1);
                    else
                        *(float2*)((float*)Cout + (size_t)rt * Nc + gc) = make_float2(v0, v1);
                    s0 += v0; s1 += v1; q0 += v0 * v0; q1 += v1 * v1;
                }
                if (rt + 8 < M) {
                    float v2 = acc[mi][ni][2] + b0;
                    float v3 = acc[mi][ni][3] + b1;
                    if (OUTH)
                        *(unsigned*)((__half*)Cout + (size_t)(rt + 8) * Nc + gc) = pack_h2(v2, v3);
                    else
                        *(float2*)((float*)Cout + (size_t)(rt + 8) * Nc + gc) = make_float2(v2, v3);
                    s0 += v2; s1 += v3; q0 += v2 * v2; q1 += v3 * v3;
                }
            }
            atomicAdd(&csum[cl], s0);
            atomicAdd(&csum[cl + 1], s1);
            atomicAdd(&csq[cl], q0);
            atomicAdd(&csq[cl + 1], q1);
        }
        __syncthreads();
        if (tid < 64 && col0 + tid < Nc) {
            atomicAdd(&bnsum[col0 + tid], csum[tid]);
            atomicAdd(&bnsq[col0 + tid], csq[tid]);
        }
    }
}

// ---------------- BN finalize ----------------
__global__ void k_bn_finalize(const float* __restrict__ g, const float* __restrict__ be,
                              int d, float invN, float* __restrict__ bn,
                              float* __restrict__ scale, float* __restrict__ shift) {
    int t = threadIdx.x;
    float s = bn[t], q = bn[256 + t];
    if (t < d) {
        float mu  = s * invN;
        float var = q * invN - mu * mu;
        float rstd = rsqrtf(fmaxf(var, 0.f) + 1e-5f);
        float sc = g[t] * rstd;
        scale[t] = sc;
        shift[t] = be[t] - mu * sc;
    }
    bn[t] = 0.f;
    bn[256 + t] = 0.f;
}

// ---------------- edge head: 4 edges per warp, 8 lanes/edge, uint2 loads ----------------
__global__ __launch_bounds__(256) void k_edge_out(
    const __half* __restrict__ conv, const int* __restrict__ src, const int* __restrict__ dst,
    const float* __restrict__ scale, const float* __restrict__ shift,
    const float* __restrict__ fcw, const float* __restrict__ fcb,
    float* __restrict__ out, int E)
{
    int warp = (blockIdx.x * blockDim.x + threadIdx.x) >> 5;
    int lane = threadIdx.x & 31;
    int sub = lane & 7;            // 8 lanes per edge
    int eslot = lane >> 3;         // 4 edges per warp
    int eid = warp * 4 + eslot;
    if (eid >= E) return;
    int s = src[eid], d = dst[eid];
    const uint2* rs = (const uint2*)(conv + (size_t)s * 32);
    const uint2* rd = (const uint2*)(conv + (size_t)d * 32);
    uint2 ua = __ldg(rs + sub);    // features [4*sub, 4*sub+4)
    uint2 ub = __ldg(rd + sub);
    int f = 4 * sub;
    float4 sc = *(const float4*)(scale + f);
    float4 sh = *(const float4*)(shift + f);
    float4 fw = *(const float4*)(fcw + f);
    float2 a0 = unpack_h2(ua.x), a1 = unpack_h2(ua.y);
    float2 b0 = unpack_h2(ub.x), b1 = unpack_h2(ub.y);
    float ax = fmaxf(a0.x * sc.x + sh.x, 0.f);
    float ay = fmaxf(a0.y * sc.y + sh.y, 0.f);
    float az = fmaxf(a1.x * sc.z + sh.z, 0.f);
    float aw = fmaxf(a1.y * sc.w + sh.w, 0.f);
    float bx = fmaxf(b0.x * sc.x + sh.x, 0.f);
    float by = fmaxf(b0.y * sc.y + sh.y, 0.f);
    float bz = fmaxf(b1.x * sc.z + sh.z, 0.f);
    float bw = fmaxf(b1.y * sc.w + sh.w, 0.f);
    float v = ax * bx * fw.x + ay * by * fw.y + az * bz * fw.z + aw * bw * fw.w;
#pragma unroll
    for (int o = 4; o; o >>= 1) v += __shfl_xor_sync(0xffffffffu, v, o);
    if (sub == 0) out[eid] = 1.f / (1.f + expf(-(v + fcb[0])));
}

// ---------------- host ----------------
extern "C" void kernel_launch(void* const* d_in, const int* in_sizes, int n_in,
                              void* d_out, int out_size)
{
    const float* x0 = (const float*)d_in[0];
    const void* ei = d_in[1];
    const float *Wl[5], *bl[5], *gl[5], *bel[5];
    for (int l = 0; l < 5; l++) {
        Wl[l]  = (const float*)d_in[2 + 4 * l];
        bl[l]  = (const float*)d_in[3 + 4 * l];
        gl[l]  = (const float*)d_in[4 + 4 * l];
        bel[l] = (const float*)d_in[5 + 4 * l];
    }
    const float* fcw = (const float*)d_in[22];
    const float* fcb = (const float*)d_in[23];
    float* out = (float*)d_out;
    const int n = NN, E = NE;
    (void)in_sizes; (void)n_in; (void)out_size;

    float *bufA, *bufB, *bufC, *di, *dis, *bn, *scale, *shift;
    int *src, *dst, *cnt, *rowptr, *woff;
    int2* csre;
    cudaGetSymbolAddress((void**)&bufA,  g_bufA);
    cudaGetSymbolAddress((void**)&bufB,  g_bufB);
    cudaGetSymbolAddress((void**)&bufC,  g_bufC);
    cudaGetSymbolAddress((void**)&src,   g_src);
    cudaGetSymbolAddress((void**)&dst,   g_dst);
    cudaGetSymbolAddress((void**)&cnt,   g_cnt);
    cudaGetSymbolAddress((void**)&rowptr,g_rowptr);
    cudaGetSymbolAddress((void**)&woff,  g_woff);
    cudaGetSymbolAddress((void**)&csre,  g_csre);
    cudaGetSymbolAddress((void**)&di,    g_di);
    cudaGetSymbolAddress((void**)&dis,   g_dis);
    cudaGetSymbolAddress((void**)&bn,    g_bn);
    cudaGetSymbolAddress((void**)&scale, g_scale);
    cudaGetSymbolAddress((void**)&shift, g_shift);

    __half* hA = (__half*)bufA;
    __half* hB = (__half*)bufB;
    __half* hC = (__half*)bufC;

    int aggBlocks = (n + 7) / 8;
    int rowBlocks = (n + 127) / 128;
    float invN = 1.0f / (float)n;

    k_prep_edges<<<2048, 256>>>(ei, src, dst, cnt, E, n);
    k_scan_deg<<<1, 1024>>>(cnt, rowptr, woff, di, dis, n);
    k_csr<<<2048, 256>>>(src, dst, dis, woff, csre, E);

    // L0 (gemm-first, fp32 A): h0h = GEMM(x0@W0) -> hA ; conv0h = aggh(h0h)+b0 -> hB (stats)
    k_gemm16<false, false, true, false><<<dim3(2, rowBlocks), 256>>>(
        x0, Wl[0], hA, n, 128, 128, nullptr, nullptr, nullptr, nullptr, nullptr);
    k_aggh<128, true, false><<<aggBlocks, 256>>>(hA, hB, rowptr, csre, di, n,
                                                 nullptr, nullptr, bl[0], bn, bn + 256);
    k_bn_finalize<<<1, 256>>>(gl[0], bel[0], 128, invN, bn, scale, shift);

    // L1 (agg-first)
    k_aggh<128, false, true><<<aggBlocks, 256>>>(hB, hA, rowptr, csre, di, n,
                                                 scale, shift, nullptr, nullptr, nullptr);
    k_gemm16<true, false, true, true><<<dim3(4, rowBlocks), 256>>>(
        hA, Wl[1], hC, n, 128, 256, nullptr, nullptr, bl[1], bn, bn + 256);
    k_bn_finalize<<<1, 256>>>(gl[1], bel[1], 256, invN, bn, scale, shift);

    // L2 (gemm-first)
    k_gemm16<false, true, true, true><<<dim3(2, rowBlocks), 256>>>(
        hC, Wl[2], hA, n, 256, 128, scale, shift, nullptr, nullptr, nullptr);
    k_aggh<128, true, false><<<aggBlocks, 256>>>(hA, hB, rowptr, csre, di, n,
                                                 nullptr, nullptr, bl[2], bn, bn + 256);
    k_bn_finalize<<<1, 256>>>(gl[2], bel[2], 128, invN, bn, scale, shift);

    // L3
    k_gemm16<false, true, true, true><<<dim3(1, rowBlocks), 256>>>(
        hB, Wl[3], hA, n, 128, 64, scale, shift, nullptr, nullptr, nullptr);
    k_aggh<64, true, false><<<aggBlocks, 256>>>(hA, hC, rowptr, csre, di, n,
                                                nullptr, nullptr, bl[3], bn, bn + 256);
    k_bn_finalize<<<1, 256>>>(gl[3], bel[3], 64, invN, bn, scale, shift);

    // L4
    k_gemm16<false, true, false, true><<<dim3(1, rowBlocks), 256>>>(
        hC, Wl[4], bufA, n, 64, 32, scale, shift, nullptr, nullptr, nullptr);
    k_agg32<<<aggBlocks, 256>>>(bufA, hB, rowptr, csre, di, n, bl[4], bn, bn + 256);
    k_bn_finalize<<<1, 256>>>(gl[4], bel[4], 32, invN, bn, scale, shift);

    // edge head: 4 edges per warp
    int edgeBlocks = (E / 4 + 7) / 8;
    k_edge_out<<<edgeBlocks, 256>>>(hB, src, dst, scale, shift, fcw, fcb, out, E);
}

// round 16
// speedup vs baseline: 1.5039x; 1.5039x over previous
#include <cuda_runtime.h>
#include <cuda_fp16.h>
#include <math.h>
#include <stdint.h>

#define NN 100000
#define NE 3200000
#define MAXD 256

typedef unsigned long long ull;

// ---------------- static device scratch (allocation-free contract) ----------------
__device__ float  g_bufA[(size_t)NN * MAXD];
__device__ float  g_bufB[(size_t)NN * MAXD];
__device__ float  g_bufC[(size_t)NN * MAXD];
__device__ int    g_src[NE];
__device__ int    g_dst[NE];
__device__ int    g_cnt[NN];       // invariant: zero at entry
__device__ int    g_rowptr[NN + 1];
__device__ int    g_woff[NN];
__device__ int2   g_csre[NE];      // packed {src, weight-bits}
__device__ float  g_di[NN];
__device__ float  g_dis[NN];
__device__ float  g_bn[512];       // invariant: zero at entry (finalize re-zeroes)
__device__ float  g_scale[256];
__device__ float  g_shift[256];

__device__ __forceinline__ unsigned pack_h2(float a, float b) {
    __half2 h = __floats2half2_rn(a, b);
    return *reinterpret_cast<unsigned*>(&h);
}
__device__ __forceinline__ float2 unpack_h2(unsigned u) {
    __half2 h = *reinterpret_cast<__half2*>(&u);
    return __half22float2(h);
}

#define MMA_F16(c, a, b)                                                               \
    asm volatile(                                                                      \
        "mma.sync.aligned.m16n8k16.row.col.f32.f16.f16.f32 "                           \
        "{%0,%1,%2,%3},{%4,%5,%6,%7},{%8,%9},{%0,%1,%2,%3};"                           \
        : "+f"((c)[0]), "+f"((c)[1]), "+f"((c)[2]), "+f"((c)[3])                       \
        : "r"((a)[0]), "r"((a)[1]), "r"((a)[2]), "r"((a)[3]), "r"((b)[0]), "r"((b)[1]))

#define LDSM_X4(r0, r1, r2, r3, addr)                                                  \
    asm volatile("ldmatrix.sync.aligned.m8n8.x4.shared.b16 {%0,%1,%2,%3}, [%4];"       \
                 : "=r"(r0), "=r"(r1), "=r"(r2), "=r"(r3) : "r"(addr))

// ---------------- prep: detect dtype inline, convert, count in-degree ----------------
__global__ void k_prep_edges(const void* __restrict__ ei_raw,
                             int* __restrict__ src, int* __restrict__ dst,
                             int* __restrict__ cnt, int E, int n) {
    const unsigned int* w = (const unsigned int*)ei_raw;
    unsigned int probe = w[2 * (threadIdx.x & 255) + 1];
    int any = __syncthreads_or(probe != 0u);
    const int is64 = (any == 0);
    const long long* ei64 = (const long long*)ei_raw;
    const int* ei32 = (const int*)ei_raw;
    for (int e = blockIdx.x * blockDim.x + threadIdx.x; e < E; e += gridDim.x * blockDim.x) {
        int s, d;
        if (is64) { s = (int)ei64[e]; d = (int)ei64[(size_t)E + e]; }
        else      { s = ei32[e];      d = ei32[(size_t)E + e]; }
        if ((unsigned)s >= (unsigned)n) s = 0;
        if ((unsigned)d >= (unsigned)n) d = 0;
        src[e] = s;
        dst[e] = d;
        atomicAdd(&cnt[d], 1);
    }
}

// ---------------- single-block tiled coalesced scan + deg + cnt re-zero ----------------
__global__ void k_scan_deg(int* __restrict__ cnt, int* __restrict__ rowptr,
                           int* __restrict__ woff, float* __restrict__ di,
                           float* __restrict__ dis, int n) {
    __shared__ int wsum[32];
    __shared__ int s_off;
    int t = threadIdx.x, lane = t & 31, wid = t >> 5;
    if (t == 0) s_off = 0;
    __syncthreads();
    for (int base = 0; base < n; base += 1024) {
        int i = base + t;
        int c = (i < n) ? cnt[i] : 0;
        if (i < n) cnt[i] = 0;
        int x = c;
#pragma unroll
        for (int o = 1; o < 32; o <<= 1) {
            int v = __shfl_up_sync(0xffffffffu, x, o);
            if (lane >= o) x += v;
        }
        if (lane == 31) wsum[wid] = x;
        __syncthreads();
        if (wid == 0) {
            int y = wsum[lane];
#pragma unroll
            for (int o = 1; o < 32; o <<= 1) {
                int v = __shfl_up_sync(0xffffffffu, y, o);
                if (lane >= o) y += v;
            }
            wsum[lane] = y;
        }
        __syncthreads();
        int wbase = (wid == 0) ? 0 : wsum[wid - 1];
        int excl = x + wbase - c;
        int off0 = s_off;
        if (i < n) {
            int r = off0 + excl;
            rowptr[i] = r;
            woff[i]   = r;
            float dg = (float)c + 1.0f;
            di[i]  = 1.0f / dg;
            dis[i] = rsqrtf(dg);
        }
        __syncthreads();
        if (t == 1023) s_off = off0 + wsum[31];
        __syncthreads();
    }
    if (t == 0) rowptr[n] = s_off;
}

// ---------------- CSR scatter with packed (src, weight) ----------------
__global__ void k_csr(const int* __restrict__ src, const int* __restrict__ dst,
                      const float* __restrict__ dis, int* __restrict__ woff,
                      int2* __restrict__ csre, int E) {
    for (int e = blockIdx.x * blockDim.x + threadIdx.x; e < E; e += gridDim.x * blockDim.x) {
        int d = dst[e];
        int pos = atomicAdd(&woff[d], 1);
        int s = src[e];
        if (pos < E) {
            float w = dis[s] * dis[d];
            csre[pos] = make_int2(s, __float_as_int(w));
        }
    }
}

// ---------------- half aggregation: warp-per-node, half2 lanes, 2-edge unroll ----------------
template <int D, bool EPI, bool AFF>
__global__ __launch_bounds__(256) void k_aggh(
    const __half* __restrict__ xin, __half* __restrict__ xout,
    const int* __restrict__ rowptr, const int2* __restrict__ csre,
    const float* __restrict__ di, int n,
    const float* __restrict__ scale, const float* __restrict__ shift,
    const float* __restrict__ bias, float* __restrict__ bnsum, float* __restrict__ bnsq)
{
    constexpr int CPL2 = D / 64;
    int lane = threadIdx.x & 31;
    int node = blockIdx.x * 8 + (threadIdx.x >> 5);
    float2 acc[CPL2];
    float2 sc[CPL2], sh[CPL2];
#pragma unroll
    for (int j = 0; j < CPL2; j++) {
        acc[j] = make_float2(0.f, 0.f);
        if (AFF) {
            int f = 2 * lane + 64 * j;
            sc[j] = make_float2(scale[f], scale[f + 1]);
            sh[j] = make_float2(shift[f], shift[f + 1]);
        }
    }

    if (node < n) {
        int beg = rowptr[node], end = rowptr[node + 1];
        int e = beg;
        for (; e + 2 <= end; e += 2) {
            int2 p0 = __ldg(&csre[e]);
            int2 p1 = __ldg(&csre[e + 1]);
            float w0 = __int_as_float(p0.y);
            float w1 = __int_as_float(p1.y);
            const __half2* r0 = (const __half2*)(xin + (size_t)p0.x * D) + lane;
            const __half2* r1 = (const __half2*)(xin + (size_t)p1.x * D) + lane;
            __half2 h0[CPL2], h1[CPL2];
#pragma unroll
            for (int j = 0; j < CPL2; j++) h0[j] = __ldg(r0 + 32 * j);
#pragma unroll
            for (int j = 0; j < CPL2; j++) h1[j] = __ldg(r1 + 32 * j);
#pragma unroll
            for (int j = 0; j < CPL2; j++) {
                float2 v0 = __half22float2(h0[j]);
                float2 v1 = __half22float2(h1[j]);
                if (AFF) {
                    v0.x = fmaxf(v0.x * sc[j].x + sh[j].x, 0.f);
                    v0.y = fmaxf(v0.y * sc[j].y + sh[j].y, 0.f);
                    v1.x = fmaxf(v1.x * sc[j].x + sh[j].x, 0.f);
                    v1.y = fmaxf(v1.y * sc[j].y + sh[j].y, 0.f);
                }
                acc[j].x += w0 * v0.x + w1 * v1.x;
                acc[j].y += w0 * v0.y + w1 * v1.y;
            }
        }
        if (e < end) {
            int2 p0 = __ldg(&csre[e]);
            float w0 = __int_as_float(p0.y);
            const __half2* r0 = (const __half2*)(xin + (size_t)p0.x * D) + lane;
#pragma unroll
            for (int j = 0; j < CPL2; j++) {
                float2 v = __half22float2(__ldg(r0 + 32 * j));
                if (AFF) {
                    v.x = fmaxf(v.x * sc[j].x + sh[j].x, 0.f);
                    v.y = fmaxf(v.y * sc[j].y + sh[j].y, 0.f);
                }
                acc[j].x += w0 * v.x;
                acc[j].y += w0 * v.y;
            }
        }
        float dii = di[node];
        const __half2* r = (const __half2*)(xin + (size_t)node * D) + lane;
        __half2* orow = (__half2*)(xout + (size_t)node * D);
#pragma unroll
        for (int j = 0; j < CPL2; j++) {
            float2 v = __half22float2(__ldg(r + 32 * j));
            if (AFF) {
                v.x = fmaxf(v.x * sc[j].x + sh[j].x, 0.f);
                v.y = fmaxf(v.y * sc[j].y + sh[j].y, 0.f);
            }
            acc[j].x += dii * v.x;
            acc[j].y += dii * v.y;
            if (EPI) {
                int f = 2 * lane + 64 * j;
                acc[j].x += bias[f];
                acc[j].y += bias[f + 1];
            }
            orow[lane + 32 * j] = __floats2half2_rn(acc[j].x, acc[j].y);
        }
    }
    if constexpr (EPI) {
        __shared__ float csum[D];
        __shared__ float csq[D];
        for (int t = threadIdx.x; t < D; t += blockDim.x) { csum[t] = 0.f; csq[t] = 0.f; }
        __syncthreads();
        if (node < n) {
#pragma unroll
            for (int j = 0; j < CPL2; j++) {
                int f = 2 * lane + 64 * j;
                atomicAdd(&csum[f], acc[j].x);
                atomicAdd(&csum[f + 1], acc[j].y);
                atomicAdd(&csq[f], acc[j].x * acc[j].x);
                atomicAdd(&csq[f + 1], acc[j].y * acc[j].y);
            }
        }
        __syncthreads();
        for (int t = threadIdx.x; t < D; t += blockDim.x) {
            atomicAdd(&bnsum[t], csum[t]);
            atomicAdd(&bnsq[t], csq[t]);
        }
    }
}

// ---------------- fp32-input aggregation (L4, D=32) -> half out + stats ----------------
__global__ __launch_bounds__(256) void k_agg32(
    const float* __restrict__ xin, __half* __restrict__ xout,
    const int* __restrict__ rowptr, const int2* __restrict__ csre,
    const float* __restrict__ di, int n,
    const float* __restrict__ bias, float* __restrict__ bnsum, float* __restrict__ bnsq)
{
    int lane = threadIdx.x & 31;
    int node = blockIdx.x * 8 + (threadIdx.x >> 5);
    float acc = 0.f;

    if (node < n) {
        int beg = rowptr[node], end = rowptr[node + 1];
        int e = beg;
        for (; e + 2 <= end; e += 2) {
            int2 p0 = __ldg(&csre[e]);
            int2 p1 = __ldg(&csre[e + 1]);
            float v0 = __ldg(xin + (size_t)p0.x * 32 + lane);
            float v1 = __ldg(xin + (size_t)p1.x * 32 + lane);
            acc += __int_as_float(p0.y) * v0;
            acc += __int_as_float(p1.y) * v1;
        }
        if (e < end) {
            int2 p0 = __ldg(&csre[e]);
            acc += __int_as_float(p0.y) * __ldg(xin + (size_t)p0.x * 32 + lane);
        }
        acc += di[node] * __ldg(xin + (size_t)node * 32 + lane);
        acc += bias[lane];
        xout[(size_t)node * 32 + lane] = __float2half_rn(acc);
    }
    __shared__ float csum[32];
    __shared__ float csq[32];
    if (threadIdx.x < 32) { csum[threadIdx.x] = 0.f; csq[threadIdx.x] = 0.f; }
    __syncthreads();
    if (node < n) {
        atomicAdd(&csum[lane], acc);
        atomicAdd(&csq[lane], acc * acc);
    }
    __syncthreads();
    if (threadIdx.x < 32) {
        atomicAdd(&bnsum[threadIdx.x], csum[threadIdx.x]);
        atomicAdd(&bnsq[threadIdx.x], csq[threadIdx.x]);
    }
}

// ---------------- fp16 tensor-core GEMM: double-buffered smem + ldmatrix ----------------
template <bool EPI, bool AFF, bool OUTH, bool A16>
__global__ __launch_bounds__(256, 3) void k_gemm16(
    const void* __restrict__ Ain, const float* __restrict__ W, void* __restrict__ Cout,
    int M, int K, int Nc,
    const float* __restrict__ scale, const float* __restrict__ shift,
    const float* __restrict__ bias, float* __restrict__ bnsum, float* __restrict__ bnsq)
{
    __shared__ unsigned As[2][128][20];
    __shared__ unsigned Bs[2][64][20];
    constexpr uint32_t A_BUF_BYTES = 128 * 20 * 4;
    constexpr uint32_t B_BUF_BYTES = 64 * 20 * 4;
    int tid = threadIdx.x;
    int row0 = blockIdx.y * 128, col0 = blockIdx.x * 64;
    int w = tid >> 5, lane = tid & 31;
    int wm = w & 3, wn = w >> 2;
    int g = lane >> 2, t = lane & 3;

    float acc[2][4][4];
#pragma unroll
    for (int mi = 0; mi < 2; mi++)
#pragma unroll
        for (int ni = 0; ni < 4; ni++)
#pragma unroll
            for (int q = 0; q < 4; q++) acc[mi][ni][q] = 0.f;

    uint32_t asb = (uint32_t)__cvta_generic_to_shared(&As[0][0][0]);
    uint32_t bsb = (uint32_t)__cvta_generic_to_shared(&Bs[0][0][0]);
    int l16 = lane & 15, kh = lane >> 4;
    int l8 = lane & 7, quad = lane >> 3;
    uint32_t aA = asb + (((wm * 32 + l16) * 20 + 4 * kh) << 2);
    uint32_t aB = bsb + (((wn * 32 + (quad >> 1) * 8 + l8) * 20 + 4 * (quad & 1)) << 2);

    uint4  pa16[2];
    float4 pa32[4];
    float  pb[4][2];

    int a16_m = tid >> 2, a16_seg = tid & 3;
    int a32_m = tid >> 3, a32_seg = tid & 7;
    int b_nn = tid & 63, b_kp0 = tid >> 6;

    const __half* A16p = (const __half*)Ain;
    const float*  A32p = (const float*)Ain;

    auto loadA = [&](int k0) {
        if (A16) {
#pragma unroll
            for (int it = 0; it < 2; it++) {
                int m = a16_m + 64 * it;
                int gm = row0 + m;
                uint4 v = make_uint4(0u, 0u, 0u, 0u);
                if (gm < M) v = *(const uint4*)(A16p + (size_t)gm * K + k0 + 8 * a16_seg);
                pa16[it] = v;
            }
        } else {
#pragma unroll
            for (int it = 0; it < 4; it++) {
                int m = a32_m + 32 * it;
                int gm = row0 + m;
                float4 v = make_float4(0.f, 0.f, 0.f, 0.f);
                if (gm < M) v = *(const float4*)(A32p + (size_t)gm * K + k0 + 4 * a32_seg);
                pa32[it] = v;
            }
        }
    };
    auto loadB = [&](int k0) {
        int gc = col0 + b_nn;
        bool ok = gc < Nc;
#pragma unroll
        for (int it = 0; it < 4; it++) {
            int kp = b_kp0 + 4 * it;
            pb[it][0] = ok ? W[(size_t)(k0 + 2 * kp) * Nc + gc] : 0.f;
            pb[it][1] = ok ? W[(size_t)(k0 + 2 * kp + 1) * Nc + gc] : 0.f;
        }
    };
    auto storeA = [&](int k0, int buf) {
        if (A16) {
#pragma unroll
            for (int it = 0; it < 2; it++) {
                int m = a16_m + 64 * it;
                uint4 v = pa16[it];
                if (AFF) {
                    unsigned* pv = &v.x;
#pragma unroll
                    for (int i = 0; i < 4; i++) {
                        float2 f = unpack_h2(pv[i]);
                        int c = k0 + 8 * a16_seg + 2 * i;
                        f.x = fmaxf(f.x * scale[c] + shift[c], 0.f);
                        f.y = fmaxf(f.y * scale[c + 1] + shift[c + 1], 0.f);
                        pv[i] = pack_h2(f.x, f.y);
                    }
                }
                *(uint4*)&As[buf][m][4 * a16_seg] = v;
            }
        } else {
#pragma unroll
            for (int it = 0; it < 4; it++) {
                int m = a32_m + 32 * it;
                float4 v = pa32[it];
                if (AFF) {
                    int c = k0 + 4 * a32_seg;
                    v.x = fmaxf(v.x * scale[c + 0] + shift[c + 0], 0.f);
                    v.y = fmaxf(v.y * scale[c + 1] + shift[c + 1], 0.f);
                    v.z = fmaxf(v.z * scale[c + 2] + shift[c + 2], 0.f);
                    v.w = fmaxf(v.w * scale[c + 3] + shift[c + 3], 0.f);
                }
                uint2 p = make_uint2(pack_h2(v.x, v.y), pack_h2(v.z, v.w));
                *(uint2*)&As[buf][m][2 * a32_seg] = p;
            }
        }
    };
    auto storeB = [&](int buf) {
#pragma unroll
        for (int it = 0; it < 4; it++) {
            int kp = b_kp0 + 4 * it;
            Bs[buf][b_nn][kp] = pack_h2(pb[it][0], pb[it][1]);
        }
    };

    loadA(0);
    loadB(0);
    storeA(0, 0);
    storeB(0);
    __syncthreads();

    const int nchunks = K >> 5;
    for (int c = 0; c < nchunks; c++) {
        int b = c & 1;
        bool more = (c + 1 < nchunks);
        if (more) {
            loadA(32 * (c + 1));
            loadB(32 * (c + 1));
        }
        uint32_t aOff = (uint32_t)b * A_BUF_BYTES;
        uint32_t bOff = (uint32_t)b * B_BUF_BYTES;
#pragma unroll
        for (int ks = 0; ks < 2; ks++) {
            uint32_t koff = (8 * ks) << 2;
            unsigned a0[4], a1[4];
            LDSM_X4(a0[0], a0[1], a0[2], a0[3], aA + aOff + koff);
            LDSM_X4(a1[0], a1[1], a1[2], a1[3], aA + aOff + koff + 16 * 20 * 4);
#pragma unroll
            for (int p = 0; p < 2; p++) {
                unsigned r0, r1, r2, r3;
                LDSM_X4(r0, r1, r2, r3, aB + bOff + koff + p * (16 * 20 * 4));
                unsigned bA[2] = {r0, r1};
                unsigned bB[2] = {r2, r3};
                MMA_F16(acc[0][2 * p + 0], a0, bA);
                MMA_F16(acc[1][2 * p + 0], a1, bA);
                MMA_F16(acc[0][2 * p + 1], a0, bB);
                MMA_F16(acc[1][2 * p + 1], a1, bB);
            }
        }
        if (more) {
            storeA(32 * (c + 1), 1 - b);
            storeB(1 - b);
            __syncthreads();
        }
    }

    if constexpr (!EPI) {
#pragma unroll
        for (int mi = 0; mi < 2; mi++) {
            int rt = row0 + wm * 32 + mi * 16 + g;
#pragma unroll
            for (int ni = 0; ni < 4; ni++) {
                int gc = col0 + wn * 32 + ni * 8 + 2 * t;
                if (gc < Nc) {
                    if (rt < M) {
                        if (OUTH)
                            *(unsigned*)((__half*)Cout + (size_t)rt * Nc + gc) =
                                pack_h2(acc[mi][ni][0], acc[mi][ni][1]);
                        else
                            *(float2*)((float*)Cout + (size_t)rt * Nc + gc) =
                                make_float2(acc[mi][ni][0], acc[mi][ni][1]);
                    }
                    if (rt + 8 < M) {
                        if (OUTH)
                            *(unsigned*)((__half*)Cout + (size_t)(rt + 8) * Nc + gc) =
                                pack_h2(acc[mi][ni][2], acc[mi][ni][3]);
                        else
                            *(float2*)((float*)Cout + (size_t)(rt + 8) * Nc + gc) =
                                make_float2(acc[mi][ni][2], acc[mi][ni][3]);
                    }
                }
            }
        }
    } else {
        __shared__ float csum[64];
        __shared__ float csq[64];
        __syncthreads();
        if (tid < 64) { csum[tid] = 0.f; csq[tid] = 0.f; }
        __syncthreads();
#pragma unroll
        for (int ni = 0; ni < 4; ni++) {
            int cl = wn * 32 + ni * 8 + 2 * t;
            int gc = col0 + cl;
            if (gc >= Nc) continue;
            float b0 = bias[gc], b1 = bias[gc + 1];
            float s0 = 0.f, s1 = 0.f, q0 = 0.f, q1 = 0.f;
#pragma unroll
            for (int mi = 0; mi < 2; mi++) {
                int rt = row0 + wm * 32 + mi * 16 + g;
                if (rt < M) {
                    float v0 = acc[mi][ni][0] + b0;
                    float v1 = acc[mi][ni][1] + b1;
                    if (OUTH)
                        *(unsigned*)((__half*)Cout + (size_t)rt * Nc + gc) = pack_h2(v0, v1);
                    else
                        *(float2*)((float*)Cout + (size_t)rt * Nc + gc) = make_float2(v0, v1);
                    s0 += v0; s1 += v1; q0 += v0 * v0; q1 += v1 * v1;
                }
                if (rt + 8 < M) {
                    float v2 = acc[mi][ni][2] + b0;
                    float v3 = acc[mi][ni][3] + b1;
                    if (OUTH)
                        *(unsigned*)((__half*)Cout + (size_t)(rt + 8) * Nc + gc) = pack_h2(v2, v3);
                    else
                        *(float2*)((float*)Cout + (size_t)(rt + 8) * Nc + gc) = make_float2(v2, v3);
                    s0 += v2; s1 += v3; q0 += v2 * v2; q1 += v3 * v3;
                }
            }
            atomicAdd(&csum[cl], s0);
            atomicAdd(&csum[cl + 1], s1);
            atomicAdd(&csq[cl], q0);
            atomicAdd(&csq[cl + 1], q1);
        }
        __syncthreads();
        if (tid < 64 && col0 + tid < Nc) {
            atomicAdd(&bnsum[col0 + tid], csum[tid]);
            atomicAdd(&bnsq[col0 + tid], csq[tid]);
        }
    }
}

// ---------------- BN finalize ----------------
__global__ void k_bn_finalize(const float* __restrict__ g, const float* __restrict__ be,
                              int d, float invN, float* __restrict__ bn,
                              float* __restrict__ scale, float* __restrict__ shift) {
    int t = threadIdx.x;
    float s = bn[t], q = bn[256 + t];
    if (t < d) {
        float mu  = s * invN;
        float var = q * invN - mu * mu;
        float rstd = rsqrtf(fmaxf(var, 0.f) + 1e-5f);
        float sc = g[t] * rstd;
        scale[t] = sc;
        shift[t] = be[t] - mu * sc;
    }
    bn[t] = 0.f;
    bn[256 + t] = 0.f;
}

// ---------------- edge head: 4 edges per warp, 8 lanes/edge, uint2 loads ----------------
__global__ __launch_bounds__(256) void k_edge_out(
    const __half* __restrict__ conv, const int* __restrict__ src, const int* __restrict__ dst,
    const float* __restrict__ scale, const float* __restrict__ shift,
    const float* __restrict__ fcw, const float* __restrict__ fcb,
    float* __restrict__ out, int E)
{
    int warp = (blockIdx.x * blockDim.x + threadIdx.x) >> 5;
    int lane = threadIdx.x & 31;
    int sub = lane & 7;            // 8 lanes per edge
    int eslot = lane >> 3;         // 4 edges per warp
    int eid = warp * 4 + eslot;
    if (eid >= E) return;
    int s = src[eid], d = dst[eid];
    const uint2* rs = (const uint2*)(conv + (size_t)s * 32);
    const uint2* rd = (const uint2*)(conv + (size_t)d * 32);
    uint2 ua = __ldg(rs + sub);    // features [4*sub, 4*sub+4)
    uint2 ub = __ldg(rd + sub);
    int f = 4 * sub;
    float4 sc = *(const float4*)(scale + f);
    float4 sh = *(const float4*)(shift + f);
    float4 fw = *(const float4*)(fcw + f);
    float2 a0 = unpack_h2(ua.x), a1 = unpack_h2(ua.y);
    float2 b0 = unpack_h2(ub.x), b1 = unpack_h2(ub.y);
    float ax = fmaxf(a0.x * sc.x + sh.x, 0.f);
    float ay = fmaxf(a0.y * sc.y + sh.y, 0.f);
    float az = fmaxf(a1.x * sc.z + sh.z, 0.f);
    float aw = fmaxf(a1.y * sc.w + sh.w, 0.f);
    float bx = fmaxf(b0.x * sc.x + sh.x, 0.f);
    float by = fmaxf(b0.y * sc.y + sh.y, 0.f);
    float bz = fmaxf(b1.x * sc.z + sh.z, 0.f);
    float bw = fmaxf(b1.y * sc.w + sh.w, 0.f);
    float v = ax * bx * fw.x + ay * by * fw.y + az * bz * fw.z + aw * bw * fw.w;
#pragma unroll
    for (int o = 4; o; o >>= 1) v += __shfl_xor_sync(0xffffffffu, v, o);
    if (sub == 0) out[eid] = 1.f / (1.f + expf(-(v + fcb[0])));
}

// ---------------- host ----------------
extern "C" void kernel_launch(void* const* d_in, const int* in_sizes, int n_in,
                              void* d_out, int out_size)
{
    const float* x0 = (const float*)d_in[0];
    const void* ei = d_in[1];
    const float *Wl[5], *bl[5], *gl[5], *bel[5];
    for (int l = 0; l < 5; l++) {
        Wl[l]  = (const float*)d_in[2 + 4 * l];
        bl[l]  = (const float*)d_in[3 + 4 * l];
        gl[l]  = (const float*)d_in[4 + 4 * l];
        bel[l] = (const float*)d_in[5 + 4 * l];
    }
    const float* fcw = (const float*)d_in[22];
    const float* fcb = (const float*)d_in[23];
    float* out = (float*)d_out;
    const int n = NN, E = NE;
    (void)in_sizes; (void)n_in; (void)out_size;

    float *bufA, *bufB, *bufC, *di, *dis, *bn, *scale, *shift;
    int *src, *dst, *cnt, *rowptr, *woff;
    int2* csre;
    cudaGetSymbolAddress((void**)&bufA,  g_bufA);
    cudaGetSymbolAddress((void**)&bufB,  g_bufB);
    cudaGetSymbolAddress((void**)&bufC,  g_bufC);
    cudaGetSymbolAddress((void**)&src,   g_src);
    cudaGetSymbolAddress((void**)&dst,   g_dst);
    cudaGetSymbolAddress((void**)&cnt,   g_cnt);
    cudaGetSymbolAddress((void**)&rowptr,g_rowptr);
    cudaGetSymbolAddress((void**)&woff,  g_woff);
    cudaGetSymbolAddress((void**)&csre,  g_csre);
    cudaGetSymbolAddress((void**)&di,    g_di);
    cudaGetSymbolAddress((void**)&dis,   g_dis);
    cudaGetSymbolAddress((void**)&bn,    g_bn);
    cudaGetSymbolAddress((void**)&scale, g_scale);
    cudaGetSymbolAddress((void**)&shift, g_shift);

    __half* hA = (__half*)bufA;
    __half* hB = (__half*)bufB;
    __half* hC = (__half*)bufC;

    int aggBlocks = (n + 7) / 8;
    int rowBlocks = (n + 127) / 128;
    float invN = 1.0f / (float)n;

    k_prep_edges<<<2048, 256>>>(ei, src, dst, cnt, E, n);
    k_scan_deg<<<1, 1024>>>(cnt, rowptr, woff, di, dis, n);
    k_csr<<<2048, 256>>>(src, dst, dis, woff, csre, E);

    // L0 (gemm-first, fp32 A): h0h = GEMM(x0@W0) -> hA ; conv0h = aggh(h0h)+b0 -> hB (stats)
    k_gemm16<false, false, true, false><<<dim3(2, rowBlocks), 256>>>(
        x0, Wl[0], hA, n, 128, 128, nullptr, nullptr, nullptr, nullptr, nullptr);
    k_aggh<128, true, false><<<aggBlocks, 256>>>(hA, hB, rowptr, csre, di, n,
                                                 nullptr, nullptr, bl[0], bn, bn + 256);
    k_bn_finalize<<<1, 256>>>(gl[0], bel[0], 128, invN, bn, scale, shift);

    // L1 (agg-first)
    k_aggh<128, false, true><<<aggBlocks, 256>>>(hB, hA, rowptr, csre, di, n,
                                                 scale, shift, nullptr, nullptr, nullptr);
    k_gemm16<true, false, true, true><<<dim3(4, rowBlocks), 256>>>(
        hA, Wl[1], hC, n, 128, 256, nullptr, nullptr, bl[1], bn, bn + 256);
    k_bn_finalize<<<1, 256>>>(gl[1], bel[1], 256, invN, bn, scale, shift);

    // L2 (gemm-first)
    k_gemm16<false, true, true, true><<<dim3(2, rowBlocks), 256>>>(
        hC, Wl[2], hA, n, 256, 128, scale, shift, nullptr, nullptr, nullptr);
    k_aggh<128, true, false><<<aggBlocks, 256>>>(hA, hB, rowptr, csre, di, n,
                                                 nullptr, nullptr, bl[2], bn, bn + 256);
    k_bn_finalize<<<1, 256>>>(gl[2], bel[2], 128, invN, bn, scale, shift);

    // L3
    k_gemm16<false, true, true, true><<<dim3(1, rowBlocks), 256>>>(
        hB, Wl[3], hA, n, 128, 64, scale, shift, nullptr, nullptr, nullptr);
    k_aggh<64, true, false><<<aggBlocks, 256>>>(hA, hC, rowptr, csre, di, n,
                                                nullptr, nullptr, bl[3], bn, bn + 256);
    k_bn_finalize<<<1, 256>>>(gl[3], bel[3], 64, invN, bn, scale, shift);

    // L4
    k_gemm16<false, true, false, true><<<dim3(1, rowBlocks), 256>>>(
        hC, Wl[4], bufA, n, 64, 32, scale, shift, nullptr, nullptr, nullptr);
    k_agg32<<<aggBlocks, 256>>>(bufA, hB, rowptr, csre, di, n, bl[4], bn, bn + 256);
    k_bn_finalize<<<1, 256>>>(gl[4], bel[4], 32, invN, bn, scale, shift);

    // edge head: 4 edges per warp
    int edgeBlocks = (E / 4 + 7) / 8;
    k_edge_out<<<edgeBlocks, 256>>>(hB, src, dst, scale, shift, fcw, fcb, out, E);
}